// round 13
// baseline (speedup 1.0000x reference)
#include <cuda_runtime.h>

// IGANN GAM: logits[b] = x[b,:]@a + bias + sum_f fc3_f(relu(fc2_f(relu(x[b,f]*W1_f+b1_f))))
// B=32768, F=256, H=16, fp32.
//
// R12: RPT=4 (W2 LDS amortized over 4 rows) + k-split into two FULLY UNROLLED
// passes (live t = t[4][4] = 32 regs; R7's spill came from the rolled pass
// loop). Fused LDS: W1/b1 interleaved {w,w,b,b}; b2/W3 interleaved per k-pair.
// ~84 regs -> 3 CTAs/SM.

typedef unsigned long long ull;

constexpr int B_TOTAL = 32768;
constexpr int F_TOTAL = 256;
constexpr int H       = 16;

constexpr int BLOCK   = 256;
constexpr int RPT     = 4;
constexpr int ROWS    = BLOCK * RPT;        // 1024
constexpr int FCHUNK  = 8;
constexpr int NCHUNK  = F_TOTAL / FCHUNK;   // 32
constexpr int NBTILE  = B_TOTAL / ROWS;     // 32
constexpr int XSTRIDE = FCHUNK + 1;         // 9 (odd: conflict-free col reads)

// smem layout (floats); 16B-aligned pair arrays first
constexpr int W2P_ELE = FCHUNK * H * (H / 2) * 2;  // 2048: [f][h][kp]{lo,hi}
constexpr int WB1_ELE = FCHUNK * H * 4;            // 512:  [f][h]{w,w,b,b}
constexpr int BW3_ELE = FCHUNK * (H / 2) * 4;      // 256:  [f][kp]{b2lo,b2hi,w3lo,w3hi}
constexpr int SX_ELE  = ROWS * XSTRIDE;            // 9216
constexpr int SMEM_FLOATS = W2P_ELE + WB1_ELE + BW3_ELE + 2 * FCHUNK + SX_ELE;
constexpr int SMEM_BYTES  = SMEM_FLOATS * (int)sizeof(float);  // ~48.2KB

__device__ __forceinline__ ull fma2(ull a, ull b, ull c) {
    ull d;
    asm("fma.rn.f32x2 %0, %1, %2, %3;" : "=l"(d) : "l"(a), "l"(b), "l"(c));
    return d;
}
__device__ __forceinline__ ull pack2(float lo, float hi) {
    ull d;
    asm("mov.b64 %0, {%1, %2};" : "=l"(d) : "f"(lo), "f"(hi));
    return d;
}
__device__ __forceinline__ void unpack2(ull v, float& lo, float& hi) {
    asm("mov.b64 {%0, %1}, %2;" : "=f"(lo), "=f"(hi) : "l"(v));
}
__device__ __forceinline__ ull relu2(ull v) {
    float lo, hi;
    unpack2(v, lo, hi);
    return pack2(fmaxf(lo, 0.0f), fmaxf(hi, 0.0f));
}

__global__ void igann_init_kernel(float* __restrict__ out,
                                  const float* __restrict__ bias_b) {
    int i = blockIdx.x * blockDim.x + threadIdx.x;
    if (i < B_TOTAL) out[i] = bias_b[0];
}

__global__ __launch_bounds__(BLOCK, 3)
void igann_kernel(const float* __restrict__ x,
                  const float* __restrict__ linear_a,
                  const float* __restrict__ W1,
                  const float* __restrict__ b1,
                  const float* __restrict__ W2,
                  const float* __restrict__ b2,
                  const float* __restrict__ W3,
                  const float* __restrict__ b3,
                  float* __restrict__ out) {
    extern __shared__ float smem[];
    float* sW2p = smem;                      // [FCHUNK][H][H/2][2]
    float* sWB1 = sW2p + W2P_ELE;            // [FCHUNK][H][4] {w,w,b,b}
    float* sBW3 = sWB1 + WB1_ELE;            // [FCHUNK][H/2][4] {b2,b2,w3,w3}
    float* sB3  = sBW3 + BW3_ELE;            // [FCHUNK]
    float* sA   = sB3  + FCHUNK;             // [FCHUNK]
    float* sx   = sA   + FCHUNK;             // [ROWS][XSTRIDE]

    const int tid  = threadIdx.x;
    const int row0 = blockIdx.x * ROWS;
    const int f0   = blockIdx.y * FCHUNK;

    // ---- stage fused small weights ----
    {
        const int wbase = f0 * H;
        for (int i = tid; i < FCHUNK * H; i += BLOCK) {
            const float w  = W1[wbase + i];
            const float bb = b1[wbase + i];
            sWB1[4 * i + 0] = w;  sWB1[4 * i + 1] = w;
            sWB1[4 * i + 2] = bb; sWB1[4 * i + 3] = bb;
        }
        for (int i = tid; i < FCHUNK * (H / 2); i += BLOCK) {
            const int f  = i >> 3;
            const int kp = i & 7;
            const float* b2s = b2 + (f0 + f) * H + 2 * kp;
            const float* w3s = W3 + (f0 + f) * H + 2 * kp;
            sBW3[4 * i + 0] = b2s[0]; sBW3[4 * i + 1] = b2s[1];
            sBW3[4 * i + 2] = w3s[0]; sBW3[4 * i + 3] = w3s[1];
        }
        if (tid < FCHUNK) {
            sB3[tid] = b3[f0 + tid];
            sA[tid]  = linear_a[f0 + tid];
        }
    }
    // ---- stage W2 k-pair interleaved: sW2p[f][h][kp] = {W2[f][2kp][h], W2[f][2kp+1][h]}
    for (int i = tid; i < FCHUNK * H * (H / 2); i += BLOCK) {
        const int f  = i >> 7;
        const int h  = (i >> 3) & 15;
        const int kp = i & 7;
        const float* src = W2 + (f0 + f) * (H * H) + h;
        sW2p[2 * i]     = src[(2 * kp) * H];
        sW2p[2 * i + 1] = src[(2 * kp + 1) * H];
    }
    // ---- stage x tile: float4 global loads ----
    for (int i = tid; i < ROWS * (FCHUNK / 4); i += BLOCK) {
        const int r = i >> 1;           // 2 quads per row
        const int q = i & 1;
        const float4 v = *(const float4*)(x + (row0 + r) * F_TOTAL + f0 + 4 * q);
        float* dst = sx + r * XSTRIDE + 4 * q;
        dst[0] = v.x; dst[1] = v.y; dst[2] = v.z; dst[3] = v.w;
    }
    __syncthreads();

    float accL[RPT];
    ull   accP[RPT];
    #pragma unroll
    for (int r = 0; r < RPT; ++r) { accL[r] = 0.0f; accP[r] = pack2(0.0f, 0.0f); }

    #pragma unroll 1
    for (int f = 0; f < FCHUNK; ++f) {
        const float xv0 = sx[(tid + 0 * BLOCK) * XSTRIDE + f];
        const float xv1 = sx[(tid + 1 * BLOCK) * XSTRIDE + f];
        const float xv2 = sx[(tid + 2 * BLOCK) * XSTRIDE + f];
        const float xv3 = sx[(tid + 3 * BLOCK) * XSTRIDE + f];
        const ull xp01 = pack2(xv0, xv1);
        const ull xp23 = pack2(xv2, xv3);

        // linear term now, so xv regs die early
        {
            const float bf = sB3[f];
            const float af = sA[f];
            accL[0] = fmaf(xv0, af, accL[0] + bf);
            accL[1] = fmaf(xv1, af, accL[1] + bf);
            accL[2] = fmaf(xv2, af, accL[2] + bf);
            accL[3] = fmaf(xv3, af, accL[3] + bf);
        }

        const ulonglong2* wb1  = (const ulonglong2*)sWB1 + f * H;       // {w_pair, b_pair}
        const ull*        bw3  = (const ull*)sBW3 + f * (H / 2) * 2;    // [kp]{b2p, w3p}
        const ulonglong2* w2q  = (const ulonglong2*)sW2p + f * 64;      // 16h x 4 quads

        // two FULLY UNROLLED passes over k-space: pass p covers k-pairs 4p..4p+3
        #pragma unroll
        for (int p = 0; p < 2; ++p) {
            ull t[RPT][4];
            #pragma unroll
            for (int j = 0; j < 4; ++j) {
                const ull c = bw3[2 * (4 * p + j)];      // b2 pair
                #pragma unroll
                for (int r = 0; r < RPT; ++r) t[r][j] = c;
            }

            #pragma unroll
            for (int h = 0; h < H; ++h) {
                const ulonglong2 wb = wb1[h];            // one LDS.128: {w,w},{b,b}
                const ull hp01 = fma2(xp01, wb.x, wb.y);
                const ull hp23 = fma2(xp23, wb.x, wb.y);
                float h0, h1, h2, h3;
                unpack2(hp01, h0, h1);
                unpack2(hp23, h2, h3);
                h0 = fmaxf(h0, 0.0f); h1 = fmaxf(h1, 0.0f);
                h2 = fmaxf(h2, 0.0f); h3 = fmaxf(h3, 0.0f);
                ull d[RPT];
                d[0] = pack2(h0, h0);
                d[1] = pack2(h1, h1);
                d[2] = pack2(h2, h2);
                d[3] = pack2(h3, h3);
                const ulonglong2 wa = w2q[h * 4 + 2 * p];       // k-pairs 4p,4p+1
                const ulonglong2 wc = w2q[h * 4 + 2 * p + 1];   // k-pairs 4p+2,4p+3
                #pragma unroll
                for (int r = 0; r < RPT; ++r) {
                    t[r][0] = fma2(d[r], wa.x, t[r][0]);
                    t[r][1] = fma2(d[r], wa.y, t[r][1]);
                    t[r][2] = fma2(d[r], wc.x, t[r][2]);
                    t[r][3] = fma2(d[r], wc.y, t[r][3]);
                }
            }

            // epilogue for this k half: accP += relu2(t) * w3 pair
            #pragma unroll
            for (int j = 0; j < 4; ++j) {
                const ull w3 = bw3[2 * (4 * p + j) + 1];  // w3 pair
                #pragma unroll
                for (int r = 0; r < RPT; ++r)
                    accP[r] = fma2(relu2(t[r][j]), w3, accP[r]);
            }
        }
    }

    #pragma unroll
    for (int r = 0; r < RPT; ++r) {
        float lo, hi;
        unpack2(accP[r], lo, hi);
        atomicAdd(&out[row0 + tid + r * BLOCK], accL[r] + lo + hi);
    }
}

extern "C" void kernel_launch(void* const* d_in, const int* in_sizes, int n_in,
                              void* d_out, int out_size) {
    const float* x        = (const float*)d_in[0];
    const float* linear_a = (const float*)d_in[1];
    const float* bias_b   = (const float*)d_in[2];
    const float* W1       = (const float*)d_in[3];
    const float* b1       = (const float*)d_in[4];
    const float* W2       = (const float*)d_in[5];
    const float* b2       = (const float*)d_in[6];
    const float* W3       = (const float*)d_in[7];
    const float* b3       = (const float*)d_in[8];
    float* out = (float*)d_out;

    cudaFuncSetAttribute(igann_kernel,
                         cudaFuncAttributeMaxDynamicSharedMemorySize, SMEM_BYTES);

    igann_init_kernel<<<(B_TOTAL + 255) / 256, 256>>>(out, bias_b);

    dim3 grid(NBTILE, NCHUNK);
    igann_kernel<<<grid, BLOCK, SMEM_BYTES>>>(x, linear_a, W1, b1, W2, b2, W3, b3, out);
}

// round 17
// speedup vs baseline: 4.8488x; 4.8488x over previous
#include <cuda_runtime.h>

// IGANN GAM — R13 ALGORITHMIC REWRITE.
// Each feature's subnet out_f(x) + a_f*x + b3_f is a piecewise-linear scalar
// function of x. Tabulate it on a uniform grid (eval at 2049 points = 1/8 the
// original FLOPs), convert to per-cell {slope, intercept}, then the main pass
// is one fused-multiply-add per (b, f) from a smem-staged table.
//
// logits[b] = bias_b + sum_f tab_f(x[b,f])

typedef float2 f2;

constexpr int B_TOTAL = 32768;
constexpr int F_TOTAL = 256;
constexpr int H       = 16;

constexpr int   NGRID = 2048;              // cells
constexpr int   NPTS  = NGRID + 1;         // grid points
constexpr float X0    = -8.0f;
constexpr float DXF   = 16.0f / NGRID;     // 0.0078125
constexpr float INVDX = NGRID / 16.0f;     // 128.0

constexpr int GV_STRIDE = NPTS + 3;        // 2052 (pad)

__device__ float  d_gval[F_TOTAL * GV_STRIDE];   // grid values
__device__ float2 d_gtab[F_TOTAL * NGRID];       // {slope, intercept} per cell

// ---- main-pass tiling ----
constexpr int MBLOCK  = 256;
constexpr int FC      = 4;                 // features per block
constexpr int FBLK    = F_TOTAL / FC;      // 64
constexpr int ROWS_PB = 4096;
constexpr int BTILES  = B_TOTAL / ROWS_PB; // 8
constexpr int MSMEM   = FC * NGRID * (int)sizeof(float2);  // 65536 B

// ============================ kernels ============================

__global__ void igann_init_kernel(float* __restrict__ out,
                                  const float* __restrict__ bias_b) {
    int i = blockIdx.x * blockDim.x + threadIdx.x;
    if (i < B_TOTAL) out[i] = bias_b[0];
}

// One block per feature: evaluate g_f at all grid points.
__global__ __launch_bounds__(256)
void igann_eval_kernel(const float* __restrict__ linear_a,
                       const float* __restrict__ W1,
                       const float* __restrict__ b1,
                       const float* __restrict__ W2,
                       const float* __restrict__ b2,
                       const float* __restrict__ W3,
                       const float* __restrict__ b3) {
    __shared__ __align__(16) float sW2[H * H];
    __shared__ float sW1[H], sB1[H], sB2[H], sW3[H];
    __shared__ float sA, sB3;

    const int f   = blockIdx.x;
    const int tid = threadIdx.x;

    if (tid < H * H) sW2[tid] = W2[f * H * H + tid];
    if (tid < H) {
        sW1[tid] = W1[f * H + tid];
        sB1[tid] = b1[f * H + tid];
        sB2[tid] = b2[f * H + tid];
        sW3[tid] = W3[f * H + tid];
    }
    if (tid == 0) { sA = linear_a[f]; sB3 = b3[f]; }
    __syncthreads();

    // two points per iteration so each weight load feeds 2 FMAs
    for (int i0 = tid; i0 < NPTS; i0 += 512) {
        const int  i1   = i0 + 256;
        const bool has2 = (i1 < NPTS);
        const float xa = X0 + i0 * DXF;
        const float xb = X0 + i1 * DXF;

        float h1a[H], h1b[H];
        #pragma unroll
        for (int h = 0; h < H; ++h) {
            h1a[h] = fmaxf(fmaf(xa, sW1[h], sB1[h]), 0.0f);
            h1b[h] = fmaxf(fmaf(xb, sW1[h], sB1[h]), 0.0f);
        }
        float acca = 0.0f, accb = 0.0f;
        #pragma unroll
        for (int k = 0; k < H; ++k) {
            float ta = sB2[k], tb = sB2[k];
            const float4* wq = (const float4*)(sW2 + k * H);
            #pragma unroll
            for (int q = 0; q < 4; ++q) {
                const float4 w = wq[q];
                ta = fmaf(h1a[4 * q + 0], w.x, ta);  tb = fmaf(h1b[4 * q + 0], w.x, tb);
                ta = fmaf(h1a[4 * q + 1], w.y, ta);  tb = fmaf(h1b[4 * q + 1], w.y, tb);
                ta = fmaf(h1a[4 * q + 2], w.z, ta);  tb = fmaf(h1b[4 * q + 2], w.z, tb);
                ta = fmaf(h1a[4 * q + 3], w.w, ta);  tb = fmaf(h1b[4 * q + 3], w.w, tb);
            }
            ta = fmaxf(ta, 0.0f);
            tb = fmaxf(tb, 0.0f);
            acca = fmaf(ta, sW3[k], acca);
            accb = fmaf(tb, sW3[k], accb);
        }
        d_gval[f * GV_STRIDE + i0] = fmaf(sA, xa, acca + sB3);
        if (has2) d_gval[f * GV_STRIDE + i1] = fmaf(sA, xb, accb + sB3);
    }
}

// Convert grid values to per-cell {slope, intercept}.
__global__ __launch_bounds__(256)
void igann_build_kernel() {
    const int idx = blockIdx.x * blockDim.x + threadIdx.x;
    if (idx >= F_TOTAL * NGRID) return;
    const int f = idx >> 11;             // / NGRID
    const int i = idx & (NGRID - 1);
    const float v0 = d_gval[f * GV_STRIDE + i];
    const float v1 = d_gval[f * GV_STRIDE + i + 1];
    const float slope = (v1 - v0) * INVDX;
    const float xi = X0 + i * DXF;
    float2 sc;
    sc.x = slope;
    sc.y = fmaf(-slope, xi, v0);         // y = slope*x + c, exact at cell ends
    d_gtab[idx] = sc;
}

// Main pass: table lookup + FMA per (b, f).
__global__ __launch_bounds__(MBLOCK)
void igann_main_kernel(const float* __restrict__ x,
                       float* __restrict__ out) {
    extern __shared__ float2 stab[];     // [FC][NGRID]
    const int tid  = threadIdx.x;
    const int row0 = blockIdx.x * ROWS_PB;
    const int f0   = blockIdx.y * FC;

    for (int i = tid; i < FC * NGRID; i += MBLOCK)
        stab[i] = d_gtab[f0 * NGRID + i];
    __syncthreads();

    for (int r = tid; r < ROWS_PB; r += MBLOCK) {
        const int row = row0 + r;
        const float4 xv = *(const float4*)(x + row * F_TOTAL + f0);
        float acc = 0.0f;
        {
            const float xj = xv.x;
            int i = __float2int_rd((xj - X0) * INVDX);
            i = max(0, min(i, NGRID - 1));
            const float2 sc = stab[0 * NGRID + i];
            acc += fmaf(sc.x, xj, sc.y);
        }
        {
            const float xj = xv.y;
            int i = __float2int_rd((xj - X0) * INVDX);
            i = max(0, min(i, NGRID - 1));
            const float2 sc = stab[1 * NGRID + i];
            acc += fmaf(sc.x, xj, sc.y);
        }
        {
            const float xj = xv.z;
            int i = __float2int_rd((xj - X0) * INVDX);
            i = max(0, min(i, NGRID - 1));
            const float2 sc = stab[2 * NGRID + i];
            acc += fmaf(sc.x, xj, sc.y);
        }
        {
            const float xj = xv.w;
            int i = __float2int_rd((xj - X0) * INVDX);
            i = max(0, min(i, NGRID - 1));
            const float2 sc = stab[3 * NGRID + i];
            acc += fmaf(sc.x, xj, sc.y);
        }
        atomicAdd(&out[row], acc);
    }
}

// ============================ launch ============================

extern "C" void kernel_launch(void* const* d_in, const int* in_sizes, int n_in,
                              void* d_out, int out_size) {
    const float* x        = (const float*)d_in[0];
    const float* linear_a = (const float*)d_in[1];
    const float* bias_b   = (const float*)d_in[2];
    const float* W1       = (const float*)d_in[3];
    const float* b1       = (const float*)d_in[4];
    const float* W2       = (const float*)d_in[5];
    const float* b2       = (const float*)d_in[6];
    const float* W3       = (const float*)d_in[7];
    const float* b3       = (const float*)d_in[8];
    float* out = (float*)d_out;

    cudaFuncSetAttribute(igann_main_kernel,
                         cudaFuncAttributeMaxDynamicSharedMemorySize, MSMEM);

    igann_init_kernel<<<(B_TOTAL + 255) / 256, 256>>>(out, bias_b);

    igann_eval_kernel<<<F_TOTAL, 256>>>(linear_a, W1, b1, W2, b2, W3, b3);

    igann_build_kernel<<<(F_TOTAL * NGRID) / 256, 256>>>();

    dim3 mgrid(BTILES, FBLK);
    igann_main_kernel<<<mgrid, MBLOCK, MSMEM>>>(x, out);
}